// round 14
// baseline (speedup 1.0000x reference)
#include <cuda_runtime.h>
#include <cuda_bf16.h>
#include <math.h>
#include <stdint.h>

// Problem constants
#define NB 1024
#define ND 512
#define NC 100000

static constexpr float S_SCALE = 30.0f;
static constexpr float COS_M   = 0.9553364891256060f;   // cos(0.3)
static constexpr float SIN_M   = 0.2955202066613396f;   // sin(0.3)
static constexpr float TH      = -0.9553364891256060f;  // cos(pi-0.3)
static constexpr float MM      = 0.0886560619984019f;   // sin(pi-0.3)*0.3
static constexpr float EPS     = 1e-12f;
static constexpr float LOG2E   = 1.4426950408889634f;
static constexpr float K1      = S_SCALE * LOG2E;        // exp(30c-30) = 2^(c*K1 + K0)
static constexpr float K0      = -S_SCALE * LOG2E;

// GEMM tiling (fp8) — R9 configuration
static constexpr int BN      = 128;                 // classes per chunk
static constexpr int NCHUNK  = (NC + BN - 1) / BN;  // 782
static constexpr int SLICE_M = 128;                 // rows per m-slice
static constexpr int NSLICE  = NB / SLICE_M;        // 8
static constexpr int BK      = 128;                 // K fp8 elements per A tile
static constexpr int NKS     = ND / BK;             // 4
static constexpr int NT      = NSLICE * NKS;        // 32 flat tiles per CTA

// smem geometry (bytes) — pad-free, XOR-swizzled
static constexpr int B_ROW    = 512;
static constexpr int A_ROW    = 128;
static constexpr int SZ_B     = BN * B_ROW;         // 65536
static constexpr int A_STRIDE = SLICE_M * A_ROW;    // 16384 per stage
static constexpr int NSTAGE   = 3;
static constexpr int SM_TOTAL = SZ_B + NSTAGE * A_STRIDE;  // 114688 -> 2 CTAs/SM

// Scratch (__device__ globals; no runtime alloc allowed)
__device__ float    g_fhat[NB * ND];              // normalized features fp32 (exact k_cost)
__device__ uint8_t  g_f8[NB * ND];                // normalized features e4m3
__device__ uint8_t  g_w8[(size_t)NC * ND];        // normalized weights e4m3 (~50 MB)
__device__ float    g_ps[2][(size_t)NB * NCHUNK]; // per (plane,row,chunk) partial sums
__device__ float    g_lse[NB];
__device__ float    g_cost[NB];

// ---------------------------------------------------------------------------
// PTX helpers (plain sm_103 ISA: ldmatrix / mma.sync fp8 / cp.async / cvt e4m3)
// ---------------------------------------------------------------------------
__device__ __forceinline__ uint32_t smem_u32(const void* p) {
    uint32_t a;
    asm("{ .reg .u64 t; cvta.to.shared.u64 t, %1; cvt.u32.u64 %0, t; }" : "=r"(a) : "l"(p));
    return a;
}

__device__ __forceinline__ uint32_t pack_e4m3(float x0, float x1, float x2, float x3) {
    uint16_t lo, hi;
    asm("cvt.rn.satfinite.e4m3x2.f32 %0, %1, %2;" : "=h"(lo) : "f"(x1), "f"(x0));
    asm("cvt.rn.satfinite.e4m3x2.f32 %0, %1, %2;" : "=h"(hi) : "f"(x3), "f"(x2));
    return (uint32_t)lo | ((uint32_t)hi << 16);
}

#define LDSM_X4(r0, r1, r2, r3, addr) \
    asm volatile("ldmatrix.sync.aligned.m8n8.x4.shared.b16 {%0,%1,%2,%3}, [%4];" \
                 : "=r"(r0), "=r"(r1), "=r"(r2), "=r"(r3) : "r"(addr))

#define MMA_FP8(d, a, b0, b1) \
    asm volatile("mma.sync.aligned.m16n8k32.row.col.f32.e4m3.e4m3.f32 " \
                 "{%0,%1,%2,%3}, {%4,%5,%6,%7}, {%8,%9}, {%0,%1,%2,%3};" \
                 : "+f"((d)[0]), "+f"((d)[1]), "+f"((d)[2]), "+f"((d)[3]) \
                 : "r"((a)[0]), "r"((a)[1]), "r"((a)[2]), "r"((a)[3]), \
                   "r"(b0), "r"(b1))

#define CP16(dst, src) \
    asm volatile("cp.async.cg.shared.global [%0], [%1], 16;" :: "r"(dst), "l"(src))
#define CP16Z(dst, src, sz) \
    asm volatile("cp.async.cg.shared.global [%0], [%1], 16, %2;" :: "r"(dst), "l"(src), "r"(sz))
#define CP_COMMIT() asm volatile("cp.async.commit_group;" ::: "memory")

// 16B-unit XOR swizzle within 128B groups
__device__ __forceinline__ uint32_t swz(uint32_t r, uint32_t c) {
    return (c ^ (r & 7u)) * 16u;
}

// ---------------------------------------------------------------------------
// Kernel 1: normalize features -> fp32 + e4m3. grid=1024, block=128
// ---------------------------------------------------------------------------
__global__ void k_norm_feat(const float* __restrict__ f) {
    int b = blockIdx.x;
    int t = threadIdx.x;
    float4 v = reinterpret_cast<const float4*>(f + (size_t)b * ND)[t];
    float ss = v.x * v.x + v.y * v.y + v.z * v.z + v.w * v.w;
    #pragma unroll
    for (int o = 16; o; o >>= 1) ss += __shfl_xor_sync(0xFFFFFFFFu, ss, o);
    __shared__ float sw[4];
    if ((t & 31) == 0) sw[t >> 5] = ss;
    __syncthreads();
    float tot = sw[0] + sw[1] + sw[2] + sw[3];
    float inv = 1.0f / fmaxf(sqrtf(tot), EPS);
    float4 o4 = make_float4(v.x * inv, v.y * inv, v.z * inv, v.w * inv);
    reinterpret_cast<float4*>(g_fhat + (size_t)b * ND)[t] = o4;
    reinterpret_cast<uint32_t*>(g_f8 + (size_t)b * ND)[t] =
        pack_e4m3(o4.x, o4.y, o4.z, o4.w);
}

// ---------------------------------------------------------------------------
// Kernel 2: weight norms + normalized e4m3 copy. One warp per row.
// ---------------------------------------------------------------------------
__global__ void k_wconv(const float* __restrict__ w) {
    int row = blockIdx.x * 8 + (threadIdx.x >> 5);
    if (row >= NC) return;
    int lane = threadIdx.x & 31;
    const float4* p = reinterpret_cast<const float4*>(w + (size_t)row * ND);
    float4 v[4];
    float ss = 0.0f;
    #pragma unroll
    for (int i = 0; i < 4; i++) {
        v[i] = p[lane * 4 + i];                  // lane owns 16 contiguous floats
        ss += v[i].x * v[i].x + v[i].y * v[i].y + v[i].z * v[i].z + v[i].w * v[i].w;
    }
    #pragma unroll
    for (int o = 16; o; o >>= 1) ss += __shfl_xor_sync(0xFFFFFFFFu, ss, o);
    float winv = 1.0f / fmaxf(sqrtf(ss), EPS);
    uint4 u;
    u.x = pack_e4m3(v[0].x * winv, v[0].y * winv, v[0].z * winv, v[0].w * winv);
    u.y = pack_e4m3(v[1].x * winv, v[1].y * winv, v[1].z * winv, v[1].w * winv);
    u.z = pack_e4m3(v[2].x * winv, v[2].y * winv, v[2].z * winv, v[2].w * winv);
    u.w = pack_e4m3(v[3].x * winv, v[3].y * winv, v[3].z * winv, v[3].w * winv);
    reinterpret_cast<uint4*>(g_w8 + (size_t)row * ND)[lane] = u;
}

// ---------------------------------------------------------------------------
// Kernel 3: fp8 mma.sync GEMM + exp-domain epilogue.  (R9 shape + kh rotation)
// grid = 782, block = 256 (8 warps, 4Mx2N, 32x64 per-warp tiles), 2 CTAs/SM.
// B [128x512] fp8 smem-resident; A 3-stage cp.async pipeline; one
// __syncthreads per tile; all 6 LDSMs batched before the 16-MMA chain.
// Each warp walks kh groups in rotated order (start = wid & 3) so that the
// post-barrier LDSM/MMA phases of the 8 warps interleave instead of colliding.
// ---------------------------------------------------------------------------
__device__ __forceinline__ void load_a_tile(uint32_t sA, int t, int tid) {
    const int msl = t >> 2;
    const int ks  = t & 3;
    const uint32_t base = sA + (uint32_t)(t % NSTAGE) * A_STRIDE;
    #pragma unroll
    for (int i = 0; i < 4; i++) {
        int u = i * 256 + tid;           // 0..1023
        uint32_t r = (uint32_t)u >> 3;   // 0..127
        uint32_t c = (uint32_t)u & 7;    // 16B unit within 128B row
        uint32_t dst = base + r * A_ROW + swz(r, c);
        const void* src = g_f8 + (size_t)(msl * SLICE_M + (int)r) * ND + ks * BK + (int)c * 16;
        CP16(dst, src);
    }
}

__global__ void __launch_bounds__(256, 2) k_mma() {
    extern __shared__ char smem[];
    const uint32_t sB = smem_u32(smem);
    const uint32_t sA = sB + SZ_B;
    const int tid    = threadIdx.x;
    const int lane   = tid & 31;
    const int wid    = tid >> 5;
    const int warp_m = wid & 3;     // 0..3 (M, 32 rows each)
    const int warp_n = wid >> 2;    // 0..1 (N, 64 cols each)
    const int chunk  = blockIdx.x;
    const int colBase = chunk * BN;
    const int khrot  = wid & 3;     // per-warp kh phase rotation

    // ---- prologue: group0 = {A0, B}; group1 = {A1} ----
    load_a_tile(sA, 0, tid);
    #pragma unroll
    for (int i = 0; i < 16; i++) {
        int u = i * 256 + tid;           // 0..4095
        uint32_t r = (uint32_t)u >> 5;   // 0..127 class row
        uint32_t c = (uint32_t)u & 31;   // 16B unit within 512B row
        uint32_t coff = ((c & 24u) | ((c & 7u) ^ (r & 7u))) * 16u;
        uint32_t dst = sB + r * B_ROW + coff;
        const void* src = g_w8 + (size_t)(colBase + (int)r) * ND + (int)c * 16;
        uint32_t sz = (colBase + (int)r < NC) ? 16u : 0u;
        CP16Z(dst, src, sz);
    }
    CP_COMMIT();
    load_a_tile(sA, 1, tid);
    CP_COMMIT();

    // per-thread LDSM base offsets (tile-invariant)
    uint32_t aoffs[2][4], boffs[4][4];
    #pragma unroll
    for (int mt = 0; mt < 2; mt++) {
        uint32_t r = (uint32_t)(warp_m * 32 + mt * 16 + (lane & 15));
        #pragma unroll
        for (int kh = 0; kh < 4; kh++) {
            uint32_t c = (uint32_t)(kh * 2 + (lane >> 4));
            aoffs[mt][kh] = r * A_ROW + swz(r, c);
        }
    }
    #pragma unroll
    for (int ng = 0; ng < 4; ng++) {
        uint32_t r = (uint32_t)(warp_n * 64 + ng * 16 + (lane & 7) + ((lane >> 4) << 3));
        #pragma unroll
        for (int kh = 0; kh < 4; kh++) {
            uint32_t c = (uint32_t)(kh * 2 + ((lane >> 3) & 1));
            boffs[ng][kh] = sB + r * B_ROW + swz(r, c);
        }
    }

    float d[2][8][4];

    #pragma unroll 1
    for (int t = 0; t < NT; t++) {
        // zero accumulators for a fresh m-slice BEFORE the wait (no smem dep)
        if ((t & 3) == 0) {
            #pragma unroll
            for (int mt = 0; mt < 2; mt++)
                #pragma unroll
                for (int nt = 0; nt < 8; nt++)
                    #pragma unroll
                    for (int j = 0; j < 4; j++) d[mt][nt][j] = 0.0f;
        }

        if (t < NT - 1) {
            asm volatile("cp.async.wait_group 1;" ::: "memory");
        } else {
            asm volatile("cp.async.wait_group 0;" ::: "memory");
        }
        __syncthreads();   // tile t visible; all warps past reads of buf[(t-1)%3]
        if (t + 2 < NT) {
            load_a_tile(sA, t + 2, tid);
            CP_COMMIT();
        }

        const uint32_t aBase = sA + (uint32_t)(t % NSTAGE) * A_STRIDE;
        #pragma unroll
        for (int j4 = 0; j4 < 4; j4++) {          // 4 x k32, rotated per warp
            const int kh = (j4 + khrot) & 3;
            // --- all 6 LDSMs first: no LDS dependency inside the MMA chain ---
            uint32_t a[2][4], b[4][4];
            #pragma unroll
            for (int mt = 0; mt < 2; mt++)
                LDSM_X4(a[mt][0], a[mt][1], a[mt][2], a[mt][3], aBase + aoffs[mt][kh]);
            #pragma unroll
            for (int ng = 0; ng < 4; ng++)
                LDSM_X4(b[ng][0], b[ng][1], b[ng][2], b[ng][3], boffs[ng][kh]);
            // --- 16 MMAs, all operands register-resident ---
            #pragma unroll
            for (int ng = 0; ng < 4; ng++) {
                #pragma unroll
                for (int mt = 0; mt < 2; mt++) {
                    MMA_FP8(d[mt][ng * 2 + 0], a[mt], b[ng][0], b[ng][1]);
                    MMA_FP8(d[mt][ng * 2 + 1], a[mt], b[ng][2], b[ng][3]);
                }
            }
        }

        if ((t & 3) == 3) {
            // ---- epilogue for m-slice (t>>2): per-row sum of 2^(cos*K1+K0) ----
            const int msl  = t >> 2;
            const int tcol = lane & 3;
            const int g    = lane >> 2;
            #pragma unroll
            for (int mt = 0; mt < 2; mt++) {
                float s0 = 0.0f, s1 = 0.0f;
                #pragma unroll
                for (int nt = 0; nt < 8; nt++) {
                    int colg = colBase + warp_n * 64 + nt * 8 + 2 * tcol;
                    #pragma unroll
                    for (int j = 0; j < 4; j++) {
                        float x = fmaf(d[mt][nt][j], K1, K0);
                        float e;
                        asm("ex2.approx.f32 %0, %1;" : "=f"(e) : "f"(x));
                        e = (colg + (j & 1) < NC) ? e : 0.0f;
                        if (j < 2) s0 += e; else s1 += e;
                    }
                }
                s0 += __shfl_xor_sync(0xFFFFFFFFu, s0, 1);
                s0 += __shfl_xor_sync(0xFFFFFFFFu, s0, 2);
                s1 += __shfl_xor_sync(0xFFFFFFFFu, s1, 1);
                s1 += __shfl_xor_sync(0xFFFFFFFFu, s1, 2);
                if (tcol == 0) {
                    int rowg = msl * SLICE_M + warp_m * 32 + mt * 16 + g;
                    g_ps[warp_n][(size_t)rowg * NCHUNK + chunk] = s0;
                    g_ps[warp_n][(size_t)(rowg + 8) * NCHUNK + chunk] = s1;
                }
            }
        }
    }
}

// ---------------------------------------------------------------------------
// Kernel 4: exact target cosine (fp32, norm fused). grid=1024, block=128
// ---------------------------------------------------------------------------
__global__ void k_cost(const float* __restrict__ w, const int* __restrict__ tgt) {
    int b = blockIdx.x;
    int t = threadIdx.x;
    int c = tgt[b];
    float4 f = reinterpret_cast<const float4*>(g_fhat + (size_t)b * ND)[t];
    float4 ww = reinterpret_cast<const float4*>(w + (size_t)c * ND)[t];
    float d = f.x * ww.x + f.y * ww.y + f.z * ww.z + f.w * ww.w;
    float n = ww.x * ww.x + ww.y * ww.y + ww.z * ww.z + ww.w * ww.w;
    #pragma unroll
    for (int o = 16; o; o >>= 1) {
        d += __shfl_xor_sync(0xFFFFFFFFu, d, o);
        n += __shfl_xor_sync(0xFFFFFFFFu, n, o);
    }
    __shared__ float sd[4], sn[4];
    if ((t & 31) == 0) { sd[t >> 5] = d; sn[t >> 5] = n; }
    __syncthreads();
    if (t == 0) {
        float dt = sd[0] + sd[1] + sd[2] + sd[3];
        float nt = sn[0] + sn[1] + sn[2] + sn[3];
        g_cost[b] = dt / fmaxf(sqrtf(nt), EPS);
    }
}

// ---------------------------------------------------------------------------
// Kernel 5: sum partials -> LSE. grid=1024, block=256
// ---------------------------------------------------------------------------
__global__ void k_lse() {
    int row = blockIdx.x;
    int t = threadIdx.x;
    float s = 0.0f;
    for (int c = t; c < NCHUNK; c += 256)
        s += g_ps[0][(size_t)row * NCHUNK + c] + g_ps[1][(size_t)row * NCHUNK + c];
    #pragma unroll
    for (int o = 16; o; o >>= 1) s += __shfl_xor_sync(0xFFFFFFFFu, s, o);
    __shared__ float ss[8];
    if ((t & 31) == 0) ss[t >> 5] = s;
    __syncthreads();
    if (t == 0) {
        float tot = 0.0f;
        #pragma unroll
        for (int i = 0; i < 8; i++) tot += ss[i];
        g_lse[row] = S_SCALE + logf(tot);  // LSE of raw logits
    }
}

// ---------------------------------------------------------------------------
// Kernel 6: margin correction + CE mean. single block 256
// ---------------------------------------------------------------------------
__global__ void k_loss(float* __restrict__ out) {
    int t = threadIdx.x;
    float acc = 0.0f;
    for (int b = t; b < NB; b += 256) {
        float c = g_cost[b];
        float sine = sqrtf(fmaxf(1.0f - c * c, 0.0f));
        float phi = c * COS_M - sine * SIN_M;
        if (!(c > TH)) phi = c - MM;
        float L  = g_lse[b];
        float lt = S_SCALE * phi;
        float lc = S_SCALE * c;
        float corr = log1pf(expf(lt - L) - expf(lc - L));
        acc += (L + corr) - lt;
    }
    #pragma unroll
    for (int o = 16; o; o >>= 1) acc += __shfl_xor_sync(0xFFFFFFFFu, acc, o);
    __shared__ float sw[8];
    if ((t & 31) == 0) sw[t >> 5] = acc;
    __syncthreads();
    if (t == 0) {
        float tot = 0.0f;
        #pragma unroll
        for (int i = 0; i < 8; i++) tot += sw[i];
        out[0] = tot / (float)NB;
    }
}

// ---------------------------------------------------------------------------
extern "C" void kernel_launch(void* const* d_in, const int* in_sizes, int n_in,
                              void* d_out, int out_size) {
    const float* feat = (const float*)d_in[0];   // [1024, 512] f32
    const float* wt   = (const float*)d_in[1];   // [100000, 512] f32
    const int*   tgt  = (const int*)d_in[2];     // [1024] int32
    float* out = (float*)d_out;

    cudaFuncSetAttribute(k_mma, cudaFuncAttributeMaxDynamicSharedMemorySize, SM_TOTAL);

    // k_mma at launch index 3 so the bounded ncu capture profiles it.
    k_norm_feat<<<NB, 128>>>(feat);
    k_wconv<<<(NC + 7) / 8, 256>>>(wt);
    k_cost<<<NB, 128>>>(wt, tgt);
    k_mma<<<NCHUNK, 256, SM_TOTAL>>>();
    k_lse<<<NB, 256>>>();
    k_loss<<<1, 256>>>(out);
}

// round 15
// speedup vs baseline: 1.0829x; 1.0829x over previous
#include <cuda_runtime.h>
#include <cuda_bf16.h>
#include <math.h>
#include <stdint.h>

// Problem constants
#define NB 1024
#define ND 512
#define NC 100000

static constexpr float S_SCALE = 30.0f;
static constexpr float COS_M   = 0.9553364891256060f;   // cos(0.3)
static constexpr float SIN_M   = 0.2955202066613396f;   // sin(0.3)
static constexpr float TH      = -0.9553364891256060f;  // cos(pi-0.3)
static constexpr float MM      = 0.0886560619984019f;   // sin(pi-0.3)*0.3
static constexpr float EPS     = 1e-12f;
static constexpr float LOG2E   = 1.4426950408889634f;
static constexpr float K1      = S_SCALE * LOG2E;        // exp(30c-30) = 2^(c*K1 + K0)
static constexpr float K0      = -S_SCALE * LOG2E;

// GEMM tiling (fp8) — R9 configuration (the 305us k_mma)
static constexpr int BN      = 128;                 // classes per chunk
static constexpr int NCHUNK  = (NC + BN - 1) / BN;  // 782
static constexpr int SLICE_M = 128;                 // rows per m-slice
static constexpr int NSLICE  = NB / SLICE_M;        // 8
static constexpr int BK      = 128;                 // K fp8 elements per A tile
static constexpr int NKS     = ND / BK;             // 4
static constexpr int NT      = NSLICE * NKS;        // 32 flat tiles per CTA

// smem geometry (bytes) — pad-free, XOR-swizzled
static constexpr int B_ROW    = 512;
static constexpr int A_ROW    = 128;
static constexpr int SZ_B     = BN * B_ROW;         // 65536
static constexpr int A_STRIDE = SLICE_M * A_ROW;    // 16384 per stage
static constexpr int NSTAGE   = 3;
static constexpr int SM_TOTAL = SZ_B + NSTAGE * A_STRIDE;  // 114688 -> 2 CTAs/SM

// Scratch (__device__ globals; no runtime alloc allowed)
__device__ float    g_fhat[NB * ND];              // normalized features fp32 (exact k_cost)
__device__ uint8_t  g_f8[NB * ND];                // normalized features e4m3
__device__ uint8_t  g_w8[(size_t)NC * ND];        // normalized weights e4m3 (~50 MB)
__device__ float    g_ps[2][(size_t)NB * NCHUNK]; // per (plane,row,chunk) partial sums
__device__ float    g_lse[NB];
__device__ float    g_cost[NB];

// ---------------------------------------------------------------------------
// PTX helpers (plain sm_103 ISA: ldmatrix / mma.sync fp8 / cp.async / cvt e4m3)
// ---------------------------------------------------------------------------
__device__ __forceinline__ uint32_t smem_u32(const void* p) {
    uint32_t a;
    asm("{ .reg .u64 t; cvta.to.shared.u64 t, %1; cvt.u32.u64 %0, t; }" : "=r"(a) : "l"(p));
    return a;
}

__device__ __forceinline__ uint32_t pack_e4m3(float x0, float x1, float x2, float x3) {
    uint16_t lo, hi;
    asm("cvt.rn.satfinite.e4m3x2.f32 %0, %1, %2;" : "=h"(lo) : "f"(x1), "f"(x0));
    asm("cvt.rn.satfinite.e4m3x2.f32 %0, %1, %2;" : "=h"(hi) : "f"(x3), "f"(x2));
    return (uint32_t)lo | ((uint32_t)hi << 16);
}

#define LDSM_X4(r0, r1, r2, r3, addr) \
    asm volatile("ldmatrix.sync.aligned.m8n8.x4.shared.b16 {%0,%1,%2,%3}, [%4];" \
                 : "=r"(r0), "=r"(r1), "=r"(r2), "=r"(r3) : "r"(addr))

#define MMA_FP8(d, a, b0, b1) \
    asm volatile("mma.sync.aligned.m16n8k32.row.col.f32.e4m3.e4m3.f32 " \
                 "{%0,%1,%2,%3}, {%4,%5,%6,%7}, {%8,%9}, {%0,%1,%2,%3};" \
                 : "+f"((d)[0]), "+f"((d)[1]), "+f"((d)[2]), "+f"((d)[3]) \
                 : "r"((a)[0]), "r"((a)[1]), "r"((a)[2]), "r"((a)[3]), \
                   "r"(b0), "r"(b1))

#define CP16(dst, src) \
    asm volatile("cp.async.cg.shared.global [%0], [%1], 16;" :: "r"(dst), "l"(src))
#define CP16Z(dst, src, sz) \
    asm volatile("cp.async.cg.shared.global [%0], [%1], 16, %2;" :: "r"(dst), "l"(src), "r"(sz))
#define CP_COMMIT() asm volatile("cp.async.commit_group;" ::: "memory")

// 16B-unit XOR swizzle within 128B groups
__device__ __forceinline__ uint32_t swz(uint32_t r, uint32_t c) {
    return (c ^ (r & 7u)) * 16u;
}

// ---------------------------------------------------------------------------
// Kernel 1: normalize features -> fp32 + e4m3. grid=1024, block=128
// ---------------------------------------------------------------------------
__global__ void k_norm_feat(const float* __restrict__ f) {
    int b = blockIdx.x;
    int t = threadIdx.x;
    float4 v = reinterpret_cast<const float4*>(f + (size_t)b * ND)[t];
    float ss = v.x * v.x + v.y * v.y + v.z * v.z + v.w * v.w;
    #pragma unroll
    for (int o = 16; o; o >>= 1) ss += __shfl_xor_sync(0xFFFFFFFFu, ss, o);
    __shared__ float sw[4];
    if ((t & 31) == 0) sw[t >> 5] = ss;
    __syncthreads();
    float tot = sw[0] + sw[1] + sw[2] + sw[3];
    float inv = 1.0f / fmaxf(sqrtf(tot), EPS);
    float4 o4 = make_float4(v.x * inv, v.y * inv, v.z * inv, v.w * inv);
    reinterpret_cast<float4*>(g_fhat + (size_t)b * ND)[t] = o4;
    reinterpret_cast<uint32_t*>(g_f8 + (size_t)b * ND)[t] =
        pack_e4m3(o4.x, o4.y, o4.z, o4.w);
}

// ---------------------------------------------------------------------------
// Kernel 2: weight norms + normalized e4m3 copy. One warp per row.
// Fully coalesced: lane j handles float4 index (j + i*32) for both the f32
// read and the packed-u32 fp8 write (128B transactions).
// ---------------------------------------------------------------------------
__global__ void k_wconv(const float* __restrict__ w) {
    int row = blockIdx.x * 8 + (threadIdx.x >> 5);
    if (row >= NC) return;
    int lane = threadIdx.x & 31;
    const float4* p = reinterpret_cast<const float4*>(w + (size_t)row * ND);
    float4 v[4];
    float ss = 0.0f;
    #pragma unroll
    for (int i = 0; i < 4; i++) {
        v[i] = p[lane + i * 32];                 // coalesced 128B per i
        ss += v[i].x * v[i].x + v[i].y * v[i].y + v[i].z * v[i].z + v[i].w * v[i].w;
    }
    #pragma unroll
    for (int o = 16; o; o >>= 1) ss += __shfl_xor_sync(0xFFFFFFFFu, ss, o);
    float winv = 1.0f / fmaxf(sqrtf(ss), EPS);
    uint32_t* o8 = reinterpret_cast<uint32_t*>(g_w8 + (size_t)row * ND);
    #pragma unroll
    for (int i = 0; i < 4; i++) {
        o8[lane + i * 32] = pack_e4m3(v[i].x * winv, v[i].y * winv,
                                      v[i].z * winv, v[i].w * winv);
    }
}

// ---------------------------------------------------------------------------
// Kernel 3: fp8 mma.sync GEMM + exp-domain epilogue.  (exact R9 shape)
// grid = 782, block = 256 (8 warps, 4Mx2N, 32x64 per-warp tiles), 2 CTAs/SM.
// B [128x512] fp8 smem-resident; A 3-stage cp.async pipeline; one
// __syncthreads per tile; all 6 LDSMs batched before the 16-MMA chain.
// Full-chunk CTAs (781 of 782) take guard-free B-load and epilogue paths.
// ---------------------------------------------------------------------------
__device__ __forceinline__ void load_a_tile(uint32_t sA, int t, int tid) {
    const int msl = t >> 2;
    const int ks  = t & 3;
    const uint32_t base = sA + (uint32_t)(t % NSTAGE) * A_STRIDE;
    #pragma unroll
    for (int i = 0; i < 4; i++) {
        int u = i * 256 + tid;           // 0..1023
        uint32_t r = (uint32_t)u >> 3;   // 0..127
        uint32_t c = (uint32_t)u & 7;    // 16B unit within 128B row
        uint32_t dst = base + r * A_ROW + swz(r, c);
        const void* src = g_f8 + (size_t)(msl * SLICE_M + (int)r) * ND + ks * BK + (int)c * 16;
        CP16(dst, src);
    }
}

__global__ void __launch_bounds__(256, 2) k_mma() {
    extern __shared__ char smem[];
    const uint32_t sB = smem_u32(smem);
    const uint32_t sA = sB + SZ_B;
    const int tid    = threadIdx.x;
    const int lane   = tid & 31;
    const int wid    = tid >> 5;
    const int warp_m = wid & 3;     // 0..3 (M, 32 rows each)
    const int warp_n = wid >> 2;    // 0..1 (N, 64 cols each)
    const int chunk  = blockIdx.x;
    const int colBase = chunk * BN;
    const bool full  = (colBase + BN <= NC);   // 781 of 782 chunks

    // ---- prologue: group0 = {A0, B}; group1 = {A1} ----
    load_a_tile(sA, 0, tid);
    if (full) {
        #pragma unroll
        for (int i = 0; i < 16; i++) {
            int u = i * 256 + tid;           // 0..4095
            uint32_t r = (uint32_t)u >> 5;   // 0..127 class row
            uint32_t c = (uint32_t)u & 31;   // 16B unit within 512B row
            uint32_t coff = ((c & 24u) | ((c & 7u) ^ (r & 7u))) * 16u;
            uint32_t dst = sB + r * B_ROW + coff;
            const void* src = g_w8 + (size_t)(colBase + (int)r) * ND + (int)c * 16;
            CP16(dst, src);
        }
    } else {
        #pragma unroll
        for (int i = 0; i < 16; i++) {
            int u = i * 256 + tid;
            uint32_t r = (uint32_t)u >> 5;
            uint32_t c = (uint32_t)u & 31;
            uint32_t coff = ((c & 24u) | ((c & 7u) ^ (r & 7u))) * 16u;
            uint32_t dst = sB + r * B_ROW + coff;
            const void* src = g_w8 + (size_t)(colBase + (int)r) * ND + (int)c * 16;
            uint32_t sz = (colBase + (int)r < NC) ? 16u : 0u;
            CP16Z(dst, src, sz);
        }
    }
    CP_COMMIT();
    load_a_tile(sA, 1, tid);
    CP_COMMIT();

    // per-thread LDSM base offsets (tile-invariant)
    uint32_t aoffs[2][4], boffs[4][4];
    #pragma unroll
    for (int mt = 0; mt < 2; mt++) {
        uint32_t r = (uint32_t)(warp_m * 32 + mt * 16 + (lane & 15));
        #pragma unroll
        for (int kh = 0; kh < 4; kh++) {
            uint32_t c = (uint32_t)(kh * 2 + (lane >> 4));
            aoffs[mt][kh] = r * A_ROW + swz(r, c);
        }
    }
    #pragma unroll
    for (int ng = 0; ng < 4; ng++) {
        uint32_t r = (uint32_t)(warp_n * 64 + ng * 16 + (lane & 7) + ((lane >> 4) << 3));
        #pragma unroll
        for (int kh = 0; kh < 4; kh++) {
            uint32_t c = (uint32_t)(kh * 2 + ((lane >> 3) & 1));
            boffs[ng][kh] = sB + r * B_ROW + swz(r, c);
        }
    }

    float d[2][8][4];

    #pragma unroll 1
    for (int t = 0; t < NT; t++) {
        if (t < NT - 1) {
            asm volatile("cp.async.wait_group 1;" ::: "memory");
        } else {
            asm volatile("cp.async.wait_group 0;" ::: "memory");
        }
        __syncthreads();   // tile t visible; all warps past reads of buf[(t-1)%3]
        if (t + 2 < NT) {
            load_a_tile(sA, t + 2, tid);
            CP_COMMIT();
        }

        if ((t & 3) == 0) {
            #pragma unroll
            for (int mt = 0; mt < 2; mt++)
                #pragma unroll
                for (int nt = 0; nt < 8; nt++)
                    #pragma unroll
                    for (int j = 0; j < 4; j++) d[mt][nt][j] = 0.0f;
        }

        const uint32_t aBase = sA + (uint32_t)(t % NSTAGE) * A_STRIDE;
        #pragma unroll
        for (int kh = 0; kh < 4; kh++) {          // 4 x k32 within BK=128
            // --- all 6 LDSMs first: no LDS dependency inside the MMA chain ---
            uint32_t a[2][4], b[4][4];
            #pragma unroll
            for (int mt = 0; mt < 2; mt++)
                LDSM_X4(a[mt][0], a[mt][1], a[mt][2], a[mt][3], aBase + aoffs[mt][kh]);
            #pragma unroll
            for (int ng = 0; ng < 4; ng++)
                LDSM_X4(b[ng][0], b[ng][1], b[ng][2], b[ng][3], boffs[ng][kh]);
            // --- 16 MMAs, all operands register-resident ---
            #pragma unroll
            for (int ng = 0; ng < 4; ng++) {
                #pragma unroll
                for (int mt = 0; mt < 2; mt++) {
                    MMA_FP8(d[mt][ng * 2 + 0], a[mt], b[ng][0], b[ng][1]);
                    MMA_FP8(d[mt][ng * 2 + 1], a[mt], b[ng][2], b[ng][3]);
                }
            }
        }

        if ((t & 3) == 3) {
            // ---- epilogue for m-slice (t>>2): per-row sum of 2^(cos*K1+K0) ----
            const int msl  = t >> 2;
            const int tcol = lane & 3;
            const int g    = lane >> 2;
            #pragma unroll
            for (int mt = 0; mt < 2; mt++) {
                float s0 = 0.0f, s1 = 0.0f;
                if (full) {
                    // guard-free fast path (781/782 chunks)
                    #pragma unroll
                    for (int nt = 0; nt < 8; nt++) {
                        #pragma unroll
                        for (int j = 0; j < 4; j++) {
                            float x = fmaf(d[mt][nt][j], K1, K0);
                            float e;
                            asm("ex2.approx.f32 %0, %1;" : "=f"(e) : "f"(x));
                            if (j < 2) s0 += e; else s1 += e;
                        }
                    }
                } else {
                    #pragma unroll
                    for (int nt = 0; nt < 8; nt++) {
                        int colg = colBase + warp_n * 64 + nt * 8 + 2 * tcol;
                        #pragma unroll
                        for (int j = 0; j < 4; j++) {
                            float x = fmaf(d[mt][nt][j], K1, K0);
                            float e;
                            asm("ex2.approx.f32 %0, %1;" : "=f"(e) : "f"(x));
                            e = (colg + (j & 1) < NC) ? e : 0.0f;
                            if (j < 2) s0 += e; else s1 += e;
                        }
                    }
                }
                s0 += __shfl_xor_sync(0xFFFFFFFFu, s0, 1);
                s0 += __shfl_xor_sync(0xFFFFFFFFu, s0, 2);
                s1 += __shfl_xor_sync(0xFFFFFFFFu, s1, 1);
                s1 += __shfl_xor_sync(0xFFFFFFFFu, s1, 2);
                if (tcol == 0) {
                    int rowg = msl * SLICE_M + warp_m * 32 + mt * 16 + g;
                    g_ps[warp_n][(size_t)rowg * NCHUNK + chunk] = s0;
                    g_ps[warp_n][(size_t)(rowg + 8) * NCHUNK + chunk] = s1;
                }
            }
        }
    }
}

// ---------------------------------------------------------------------------
// Kernel 4: exact target cosine (fp32, norm fused). grid=1024, block=128
// ---------------------------------------------------------------------------
__global__ void k_cost(const float* __restrict__ w, const int* __restrict__ tgt) {
    int b = blockIdx.x;
    int t = threadIdx.x;
    int c = tgt[b];
    float4 f = reinterpret_cast<const float4*>(g_fhat + (size_t)b * ND)[t];
    float4 ww = reinterpret_cast<const float4*>(w + (size_t)c * ND)[t];
    float d = f.x * ww.x + f.y * ww.y + f.z * ww.z + f.w * ww.w;
    float n = ww.x * ww.x + ww.y * ww.y + ww.z * ww.z + ww.w * ww.w;
    #pragma unroll
    for (int o = 16; o; o >>= 1) {
        d += __shfl_xor_sync(0xFFFFFFFFu, d, o);
        n += __shfl_xor_sync(0xFFFFFFFFu, n, o);
    }
    __shared__ float sd[4], sn[4];
    if ((t & 31) == 0) { sd[t >> 5] = d; sn[t >> 5] = n; }
    __syncthreads();
    if (t == 0) {
        float dt = sd[0] + sd[1] + sd[2] + sd[3];
        float nt = sn[0] + sn[1] + sn[2] + sn[3];
        g_cost[b] = dt / fmaxf(sqrtf(nt), EPS);
    }
}

// ---------------------------------------------------------------------------
// Kernel 5: sum partials -> LSE. grid=1024, block=256
// ---------------------------------------------------------------------------
__global__ void k_lse() {
    int row = blockIdx.x;
    int t = threadIdx.x;
    float s = 0.0f;
    for (int c = t; c < NCHUNK; c += 256)
        s += g_ps[0][(size_t)row * NCHUNK + c] + g_ps[1][(size_t)row * NCHUNK + c];
    #pragma unroll
    for (int o = 16; o; o >>= 1) s += __shfl_xor_sync(0xFFFFFFFFu, s, o);
    __shared__ float ss[8];
    if ((t & 31) == 0) ss[t >> 5] = s;
    __syncthreads();
    if (t == 0) {
        float tot = 0.0f;
        #pragma unroll
        for (int i = 0; i < 8; i++) tot += ss[i];
        g_lse[row] = S_SCALE + logf(tot);  // LSE of raw logits
    }
}

// ---------------------------------------------------------------------------
// Kernel 6: margin correction + CE mean. single block 256
// ---------------------------------------------------------------------------
__global__ void k_loss(float* __restrict__ out) {
    int t = threadIdx.x;
    float acc = 0.0f;
    for (int b = t; b < NB; b += 256) {
        float c = g_cost[b];
        float sine = sqrtf(fmaxf(1.0f - c * c, 0.0f));
        float phi = c * COS_M - sine * SIN_M;
        if (!(c > TH)) phi = c - MM;
        float L  = g_lse[b];
        float lt = S_SCALE * phi;
        float lc = S_SCALE * c;
        float corr = log1pf(expf(lt - L) - expf(lc - L));
        acc += (L + corr) - lt;
    }
    #pragma unroll
    for (int o = 16; o; o >>= 1) acc += __shfl_xor_sync(0xFFFFFFFFu, acc, o);
    __shared__ float sw[8];
    if ((t & 31) == 0) sw[t >> 5] = acc;
    __syncthreads();
    if (t == 0) {
        float tot = 0.0f;
        #pragma unroll
        for (int i = 0; i < 8; i++) tot += sw[i];
        out[0] = tot / (float)NB;
    }
}

// ---------------------------------------------------------------------------
extern "C" void kernel_launch(void* const* d_in, const int* in_sizes, int n_in,
                              void* d_out, int out_size) {
    const float* feat = (const float*)d_in[0];   // [1024, 512] f32
    const float* wt   = (const float*)d_in[1];   // [100000, 512] f32
    const int*   tgt  = (const int*)d_in[2];     // [1024] int32
    float* out = (float*)d_out;

    cudaFuncSetAttribute(k_mma, cudaFuncAttributeMaxDynamicSharedMemorySize, SM_TOTAL);

    // k_mma at launch index 3 so the bounded ncu capture profiles it.
    k_norm_feat<<<NB, 128>>>(feat);
    k_wconv<<<(NC + 7) / 8, 256>>>(wt);
    k_cost<<<NB, 128>>>(wt, tgt);
    k_mma<<<NCHUNK, 256, SM_TOTAL>>>();
    k_lse<<<NB, 256>>>();
    k_loss<<<1, 256>>>(out);
}

// round 16
// speedup vs baseline: 1.1449x; 1.0572x over previous
#include <cuda_runtime.h>
#include <cuda_bf16.h>
#include <math.h>
#include <stdint.h>

// Problem constants
#define NB 1024
#define ND 512
#define NC 100000

static constexpr float S_SCALE = 30.0f;
static constexpr float COS_M   = 0.9553364891256060f;   // cos(0.3)
static constexpr float SIN_M   = 0.2955202066613396f;   // sin(0.3)
static constexpr float TH      = -0.9553364891256060f;  // cos(pi-0.3)
static constexpr float MM      = 0.0886560619984019f;   // sin(pi-0.3)*0.3
static constexpr float EPS     = 1e-12f;
static constexpr float LOG2E   = 1.4426950408889634f;
static constexpr float K1      = S_SCALE * LOG2E;        // exp(30c-30) = 2^(c*K1 + K0)
static constexpr float K0      = -S_SCALE * LOG2E;

// GEMM tiling (fp8) — R9 configuration (the 305us k_mma), byte-exact body
static constexpr int BN      = 128;                 // classes per chunk
static constexpr int NCHUNK  = (NC + BN - 1) / BN;  // 782
static constexpr int SLICE_M = 128;                 // rows per m-slice
static constexpr int NSLICE  = NB / SLICE_M;        // 8
static constexpr int BK      = 128;                 // K fp8 elements per A tile
static constexpr int NKS     = ND / BK;             // 4
static constexpr int NT      = NSLICE * NKS;        // 32 flat tiles per CTA

// smem geometry (bytes) — pad-free, XOR-swizzled
static constexpr int B_ROW    = 512;
static constexpr int A_ROW    = 128;
static constexpr int SZ_B     = BN * B_ROW;         // 65536
static constexpr int A_STRIDE = SLICE_M * A_ROW;    // 16384 per stage
static constexpr int NSTAGE   = 3;
static constexpr int SM_TOTAL = SZ_B + NSTAGE * A_STRIDE;  // 114688 -> 2 CTAs/SM

// Scratch (__device__ globals; no runtime alloc allowed)
__device__ uint8_t  g_f8[NB * ND];                // normalized features e4m3
__device__ uint8_t  g_w8[(size_t)NC * ND];        // normalized weights e4m3 (~50 MB)
__device__ float    g_ps[2][(size_t)NB * NCHUNK]; // per (plane,row,chunk) partial sums
__device__ float    g_lossrow[NB];                // per-row loss terms
__device__ float    g_cost[NB];                   // exact target cosine

// ---------------------------------------------------------------------------
// PTX helpers (plain sm_103 ISA: ldmatrix / mma.sync fp8 / cp.async / cvt e4m3)
// ---------------------------------------------------------------------------
__device__ __forceinline__ uint32_t smem_u32(const void* p) {
    uint32_t a;
    asm("{ .reg .u64 t; cvta.to.shared.u64 t, %1; cvt.u32.u64 %0, t; }" : "=r"(a) : "l"(p));
    return a;
}

__device__ __forceinline__ uint32_t pack_e4m3(float x0, float x1, float x2, float x3) {
    uint16_t lo, hi;
    asm("cvt.rn.satfinite.e4m3x2.f32 %0, %1, %2;" : "=h"(lo) : "f"(x1), "f"(x0));
    asm("cvt.rn.satfinite.e4m3x2.f32 %0, %1, %2;" : "=h"(hi) : "f"(x3), "f"(x2));
    return (uint32_t)lo | ((uint32_t)hi << 16);
}

#define LDSM_X4(r0, r1, r2, r3, addr) \
    asm volatile("ldmatrix.sync.aligned.m8n8.x4.shared.b16 {%0,%1,%2,%3}, [%4];" \
                 : "=r"(r0), "=r"(r1), "=r"(r2), "=r"(r3) : "r"(addr))

#define MMA_FP8(d, a, b0, b1) \
    asm volatile("mma.sync.aligned.m16n8k32.row.col.f32.e4m3.e4m3.f32 " \
                 "{%0,%1,%2,%3}, {%4,%5,%6,%7}, {%8,%9}, {%0,%1,%2,%3};" \
                 : "+f"((d)[0]), "+f"((d)[1]), "+f"((d)[2]), "+f"((d)[3]) \
                 : "r"((a)[0]), "r"((a)[1]), "r"((a)[2]), "r"((a)[3]), \
                   "r"(b0), "r"(b1))

#define CP16(dst, src) \
    asm volatile("cp.async.cg.shared.global [%0], [%1], 16;" :: "r"(dst), "l"(src))
#define CP16Z(dst, src, sz) \
    asm volatile("cp.async.cg.shared.global [%0], [%1], 16, %2;" :: "r"(dst), "l"(src), "r"(sz))
#define CP_COMMIT() asm volatile("cp.async.commit_group;" ::: "memory")

// 16B-unit XOR swizzle within 128B groups
__device__ __forceinline__ uint32_t swz(uint32_t r, uint32_t c) {
    return (c ^ (r & 7u)) * 16u;
}

// ---------------------------------------------------------------------------
// Kernel 1: normalize features -> e4m3, AND exact target cosine (fused).
// grid=1024, block=128. Block b normalizes feature row b (kept in registers),
// then dots it against weight row tgt[b] with the weight norm fused in.
// ---------------------------------------------------------------------------
__global__ void k_norm_cost(const float* __restrict__ f,
                            const float* __restrict__ w,
                            const int* __restrict__ tgt) {
    int b = blockIdx.x;
    int t = threadIdx.x;
    float4 v = reinterpret_cast<const float4*>(f + (size_t)b * ND)[t];
    float ss = v.x * v.x + v.y * v.y + v.z * v.z + v.w * v.w;
    #pragma unroll
    for (int o = 16; o; o >>= 1) ss += __shfl_xor_sync(0xFFFFFFFFu, ss, o);
    __shared__ float sw[4];
    if ((t & 31) == 0) sw[t >> 5] = ss;
    __syncthreads();
    float tot = sw[0] + sw[1] + sw[2] + sw[3];
    float inv = 1.0f / fmaxf(sqrtf(tot), EPS);
    float4 o4 = make_float4(v.x * inv, v.y * inv, v.z * inv, v.w * inv);
    reinterpret_cast<uint32_t*>(g_f8 + (size_t)b * ND)[t] =
        pack_e4m3(o4.x, o4.y, o4.z, o4.w);

    // fused exact target cosine (fp32)
    int c = tgt[b];
    float4 ww = reinterpret_cast<const float4*>(w + (size_t)c * ND)[t];
    float d = o4.x * ww.x + o4.y * ww.y + o4.z * ww.z + o4.w * ww.w;
    float n = ww.x * ww.x + ww.y * ww.y + ww.z * ww.z + ww.w * ww.w;
    #pragma unroll
    for (int o = 16; o; o >>= 1) {
        d += __shfl_xor_sync(0xFFFFFFFFu, d, o);
        n += __shfl_xor_sync(0xFFFFFFFFu, n, o);
    }
    __shared__ float sd[4], sn[4];
    if ((t & 31) == 0) { sd[t >> 5] = d; sn[t >> 5] = n; }
    __syncthreads();
    if (t == 0) {
        float dt = sd[0] + sd[1] + sd[2] + sd[3];
        float nt = sn[0] + sn[1] + sn[2] + sn[3];
        g_cost[b] = dt / fmaxf(sqrtf(nt), EPS);
    }
}

// ---------------------------------------------------------------------------
// Kernel 2: weight norms + normalized e4m3 copy. One warp per row.
// ---------------------------------------------------------------------------
__global__ void k_wconv(const float* __restrict__ w) {
    int row = blockIdx.x * 8 + (threadIdx.x >> 5);
    if (row >= NC) return;
    int lane = threadIdx.x & 31;
    const float4* p = reinterpret_cast<const float4*>(w + (size_t)row * ND);
    float4 v[4];
    float ss = 0.0f;
    #pragma unroll
    for (int i = 0; i < 4; i++) {
        v[i] = p[lane * 4 + i];                  // lane owns 16 contiguous floats
        ss += v[i].x * v[i].x + v[i].y * v[i].y + v[i].z * v[i].z + v[i].w * v[i].w;
    }
    #pragma unroll
    for (int o = 16; o; o >>= 1) ss += __shfl_xor_sync(0xFFFFFFFFu, ss, o);
    float winv = 1.0f / fmaxf(sqrtf(ss), EPS);
    uint4 u;
    u.x = pack_e4m3(v[0].x * winv, v[0].y * winv, v[0].z * winv, v[0].w * winv);
    u.y = pack_e4m3(v[1].x * winv, v[1].y * winv, v[1].z * winv, v[1].w * winv);
    u.z = pack_e4m3(v[2].x * winv, v[2].y * winv, v[2].z * winv, v[2].w * winv);
    u.w = pack_e4m3(v[3].x * winv, v[3].y * winv, v[3].z * winv, v[3].w * winv);
    reinterpret_cast<uint4*>(g_w8 + (size_t)row * ND)[lane] = u;
}

// ---------------------------------------------------------------------------
// Kernel 3: fp8 mma.sync GEMM + exp-domain epilogue.  (byte-exact R9 body)
// grid = 782, block = 256 (8 warps, 4Mx2N, 32x64 per-warp tiles), 2 CTAs/SM.
// B [128x512] fp8 smem-resident; A 3-stage cp.async pipeline; one
// __syncthreads per tile; all 6 LDSMs batched before the 16-MMA chain.
// ---------------------------------------------------------------------------
__device__ __forceinline__ void load_a_tile(uint32_t sA, int t, int tid) {
    const int msl = t >> 2;
    const int ks  = t & 3;
    const uint32_t base = sA + (uint32_t)(t % NSTAGE) * A_STRIDE;
    #pragma unroll
    for (int i = 0; i < 4; i++) {
        int u = i * 256 + tid;           // 0..1023
        uint32_t r = (uint32_t)u >> 3;   // 0..127
        uint32_t c = (uint32_t)u & 7;    // 16B unit within 128B row
        uint32_t dst = base + r * A_ROW + swz(r, c);
        const void* src = g_f8 + (size_t)(msl * SLICE_M + (int)r) * ND + ks * BK + (int)c * 16;
        CP16(dst, src);
    }
}

__global__ void __launch_bounds__(256, 2) k_mma() {
    extern __shared__ char smem[];
    const uint32_t sB = smem_u32(smem);
    const uint32_t sA = sB + SZ_B;
    const int tid    = threadIdx.x;
    const int lane   = tid & 31;
    const int wid    = tid >> 5;
    const int warp_m = wid & 3;     // 0..3 (M, 32 rows each)
    const int warp_n = wid >> 2;    // 0..1 (N, 64 cols each)
    const int chunk  = blockIdx.x;
    const int colBase = chunk * BN;

    // ---- prologue: group0 = {A0, B}; group1 = {A1} ----
    load_a_tile(sA, 0, tid);
    #pragma unroll
    for (int i = 0; i < 16; i++) {
        int u = i * 256 + tid;           // 0..4095
        uint32_t r = (uint32_t)u >> 5;   // 0..127 class row
        uint32_t c = (uint32_t)u & 31;   // 16B unit within 512B row
        uint32_t coff = ((c & 24u) | ((c & 7u) ^ (r & 7u))) * 16u;
        uint32_t dst = sB + r * B_ROW + coff;
        const void* src = g_w8 + (size_t)(colBase + (int)r) * ND + (int)c * 16;
        uint32_t sz = (colBase + (int)r < NC) ? 16u : 0u;
        CP16Z(dst, src, sz);
    }
    CP_COMMIT();
    load_a_tile(sA, 1, tid);
    CP_COMMIT();

    // per-thread LDSM base offsets (tile-invariant)
    uint32_t aoffs[2][4], boffs[4][4];
    #pragma unroll
    for (int mt = 0; mt < 2; mt++) {
        uint32_t r = (uint32_t)(warp_m * 32 + mt * 16 + (lane & 15));
        #pragma unroll
        for (int kh = 0; kh < 4; kh++) {
            uint32_t c = (uint32_t)(kh * 2 + (lane >> 4));
            aoffs[mt][kh] = r * A_ROW + swz(r, c);
        }
    }
    #pragma unroll
    for (int ng = 0; ng < 4; ng++) {
        uint32_t r = (uint32_t)(warp_n * 64 + ng * 16 + (lane & 7) + ((lane >> 4) << 3));
        #pragma unroll
        for (int kh = 0; kh < 4; kh++) {
            uint32_t c = (uint32_t)(kh * 2 + ((lane >> 3) & 1));
            boffs[ng][kh] = sB + r * B_ROW + swz(r, c);
        }
    }

    float d[2][8][4];

    #pragma unroll 1
    for (int t = 0; t < NT; t++) {
        if (t < NT - 1) {
            asm volatile("cp.async.wait_group 1;" ::: "memory");
        } else {
            asm volatile("cp.async.wait_group 0;" ::: "memory");
        }
        __syncthreads();   // tile t visible; all warps past reads of buf[(t-1)%3]
        if (t + 2 < NT) {
            load_a_tile(sA, t + 2, tid);
            CP_COMMIT();
        }

        if ((t & 3) == 0) {
            #pragma unroll
            for (int mt = 0; mt < 2; mt++)
                #pragma unroll
                for (int nt = 0; nt < 8; nt++)
                    #pragma unroll
                    for (int j = 0; j < 4; j++) d[mt][nt][j] = 0.0f;
        }

        const uint32_t aBase = sA + (uint32_t)(t % NSTAGE) * A_STRIDE;
        #pragma unroll
        for (int kh = 0; kh < 4; kh++) {          // 4 x k32 within BK=128
            // --- all 6 LDSMs first: no LDS dependency inside the MMA chain ---
            uint32_t a[2][4], b[4][4];
            #pragma unroll
            for (int mt = 0; mt < 2; mt++)
                LDSM_X4(a[mt][0], a[mt][1], a[mt][2], a[mt][3], aBase + aoffs[mt][kh]);
            #pragma unroll
            for (int ng = 0; ng < 4; ng++)
                LDSM_X4(b[ng][0], b[ng][1], b[ng][2], b[ng][3], boffs[ng][kh]);
            // --- 16 MMAs, all operands register-resident ---
            #pragma unroll
            for (int ng = 0; ng < 4; ng++) {
                #pragma unroll
                for (int mt = 0; mt < 2; mt++) {
                    MMA_FP8(d[mt][ng * 2 + 0], a[mt], b[ng][0], b[ng][1]);
                    MMA_FP8(d[mt][ng * 2 + 1], a[mt], b[ng][2], b[ng][3]);
                }
            }
        }

        if ((t & 3) == 3) {
            // ---- epilogue for m-slice (t>>2): per-row sum of 2^(cos*K1+K0) ----
            const int msl  = t >> 2;
            const int tcol = lane & 3;
            const int g    = lane >> 2;
            #pragma unroll
            for (int mt = 0; mt < 2; mt++) {
                float s0 = 0.0f, s1 = 0.0f;
                #pragma unroll
                for (int nt = 0; nt < 8; nt++) {
                    int colg = colBase + warp_n * 64 + nt * 8 + 2 * tcol;
                    #pragma unroll
                    for (int j = 0; j < 4; j++) {
                        float x = fmaf(d[mt][nt][j], K1, K0);
                        float e;
                        asm("ex2.approx.f32 %0, %1;" : "=f"(e) : "f"(x));
                        e = (colg + (j & 1) < NC) ? e : 0.0f;
                        if (j < 2) s0 += e; else s1 += e;
                    }
                }
                s0 += __shfl_xor_sync(0xFFFFFFFFu, s0, 1);
                s0 += __shfl_xor_sync(0xFFFFFFFFu, s0, 2);
                s1 += __shfl_xor_sync(0xFFFFFFFFu, s1, 1);
                s1 += __shfl_xor_sync(0xFFFFFFFFu, s1, 2);
                if (tcol == 0) {
                    int rowg = msl * SLICE_M + warp_m * 32 + mt * 16 + g;
                    g_ps[warp_n][(size_t)rowg * NCHUNK + chunk] = s0;
                    g_ps[warp_n][(size_t)(rowg + 8) * NCHUNK + chunk] = s1;
                }
            }
        }
    }
}

// ---------------------------------------------------------------------------
// Kernel 4: sum partials -> LSE -> per-row margin loss (fused).
// grid=1024, block=256
// ---------------------------------------------------------------------------
__global__ void k_lse() {
    int row = blockIdx.x;
    int t = threadIdx.x;
    float s = 0.0f;
    for (int c = t; c < NCHUNK; c += 256)
        s += g_ps[0][(size_t)row * NCHUNK + c] + g_ps[1][(size_t)row * NCHUNK + c];
    #pragma unroll
    for (int o = 16; o; o >>= 1) s += __shfl_xor_sync(0xFFFFFFFFu, s, o);
    __shared__ float ss[8];
    if ((t & 31) == 0) ss[t >> 5] = s;
    __syncthreads();
    if (t == 0) {
        float tot = 0.0f;
        #pragma unroll
        for (int i = 0; i < 8; i++) tot += ss[i];
        float L = S_SCALE + logf(tot);   // LSE of raw logits
        // fused ArcFace margin correction + per-row CE term
        float c = g_cost[row];
        float sine = sqrtf(fmaxf(1.0f - c * c, 0.0f));
        float phi = c * COS_M - sine * SIN_M;
        if (!(c > TH)) phi = c - MM;
        float lt = S_SCALE * phi;
        float lc = S_SCALE * c;
        float corr = log1pf(expf(lt - L) - expf(lc - L));
        g_lossrow[row] = (L + corr) - lt;
    }
}

// ---------------------------------------------------------------------------
// Kernel 5: mean of per-row losses. single block 256
// ---------------------------------------------------------------------------
__global__ void k_loss(float* __restrict__ out) {
    int t = threadIdx.x;
    float acc = 0.0f;
    for (int b = t; b < NB; b += 256) acc += g_lossrow[b];
    #pragma unroll
    for (int o = 16; o; o >>= 1) acc += __shfl_xor_sync(0xFFFFFFFFu, acc, o);
    __shared__ float sw[8];
    if ((t & 31) == 0) sw[t >> 5] = acc;
    __syncthreads();
    if (t == 0) {
        float tot = 0.0f;
        #pragma unroll
        for (int i = 0; i < 8; i++) tot += sw[i];
        out[0] = tot / (float)NB;
    }
}

// ---------------------------------------------------------------------------
extern "C" void kernel_launch(void* const* d_in, const int* in_sizes, int n_in,
                              void* d_out, int out_size) {
    const float* feat = (const float*)d_in[0];   // [1024, 512] f32
    const float* wt   = (const float*)d_in[1];   // [100000, 512] f32
    const int*   tgt  = (const int*)d_in[2];     // [1024] int32
    float* out = (float*)d_out;

    cudaFuncSetAttribute(k_mma, cudaFuncAttributeMaxDynamicSharedMemorySize, SM_TOTAL);

    k_norm_cost<<<NB, 128>>>(feat, wt, tgt);     // norm + exact target cosine
    k_wconv<<<(NC + 7) / 8, 256>>>(wt);
    k_mma<<<NCHUNK, 256, SM_TOTAL>>>();
    k_lse<<<NB, 256>>>();                        // LSE + fused margin loss
    k_loss<<<1, 256>>>(out);
}